// round 2
// baseline (speedup 1.0000x reference)
#include <cuda_runtime.h>

#define BB 8
#define NN 4096
#define DD 1024
#define OUTD 1024
#define PASS_BLOCKS 64      // s-partial slices per batch
#define KS 16               // k-slices in column-GEMV
#define DT 4                // d-tiles (256 cols each) in column-GEMV

// ---------------- device scratch (no allocations allowed) ----------------
__device__ __align__(16) float g_Wgm[DD * DD];
__device__ __align__(16) float g_b[BB * NN];
__device__ __align__(16) float g_c[BB * NN];
__device__ __align__(16) float g_delta[BB * NN];
__device__ __align__(16) float g_q[BB * DD];
__device__ __align__(16) float g_qt[BB * DD];
__device__ __align__(16) float g_tmp[BB * DD];
__device__ __align__(16) float g_tmp2[BB * DD];
__device__ __align__(16) float g_outv[BB * DD];
__device__ __align__(16) float g_sbuf[BB * DD];
__device__ __align__(16) float g_part[BB * PASS_BLOCKS * DD];
__device__ __align__(16) float g_cpart[KS * BB * DD];
__device__ int g_cnt[DT];   // zero-initialized

// ---------------- helpers ----------------
__device__ __forceinline__ float warpSum(float v) {
    #pragma unroll
    for (int o = 16; o; o >>= 1) v += __shfl_xor_sync(0xffffffffu, v, o);
    return v;
}
__device__ __forceinline__ float warpMax(float v) {
    #pragma unroll
    for (int o = 16; o; o >>= 1) v = fmaxf(v, __shfl_xor_sync(0xffffffffu, v, o));
    return v;
}

// softmax over 4096 values held 16/thread in v[]; writes g_c[b]. 256 threads.
__device__ __forceinline__ void softmax_store(int b, float* v) {
    __shared__ float red[8];
    int t = threadIdx.x;
    float mx = -3.0e38f;
    #pragma unroll
    for (int i = 0; i < 16; i++) mx = fmaxf(mx, v[i]);
    mx = warpMax(mx);
    if ((t & 31) == 0) red[t >> 5] = mx;
    __syncthreads();
    mx = red[0];
    #pragma unroll
    for (int w = 1; w < 8; w++) mx = fmaxf(mx, red[w]);
    float sum = 0.f;
    #pragma unroll
    for (int i = 0; i < 16; i++) { v[i] = expf(v[i] - mx); sum += v[i]; }
    sum = warpSum(sum);
    __syncthreads();
    if ((t & 31) == 0) red[t >> 5] = sum;
    __syncthreads();
    sum = 0.f;
    #pragma unroll
    for (int w = 0; w < 8; w++) sum += red[w];
    float inv = 1.0f / sum;
    #pragma unroll
    for (int i = 0; i < 16; i++) g_c[b * NN + i * 256 + t] = v[i] * inv;
}

// column-GEMV body: Y[b,d] = sum_k X[b,k] * M[k,d]. KS*DT blocks; the last
// block of each d-tile reduces the KS slices in a fixed order (deterministic).
__device__ __forceinline__ void colmv_body(const float* __restrict__ M,
                                           const float* __restrict__ X,
                                           float* __restrict__ Y, int cb) {
    int dt = cb & (DT - 1);
    int ks = cb >> 2;                 // DT == 4
    int d = dt * 256 + threadIdx.x;
    __shared__ float sx[BB][64];
    for (int i = threadIdx.x; i < BB * 64; i += 256)
        sx[i >> 6][i & 63] = X[(i >> 6) * DD + ks * 64 + (i & 63)];
    __syncthreads();
    float acc[BB];
    #pragma unroll
    for (int b = 0; b < BB; b++) acc[b] = 0.f;
    const float* Mp = M + (size_t)(ks * 64) * DD + d;
    #pragma unroll 8
    for (int k = 0; k < 64; k++) {
        float m = Mp[(size_t)k * DD];
        #pragma unroll
        for (int b = 0; b < BB; b++) acc[b] += sx[b][k] * m;
    }
    #pragma unroll
    for (int b = 0; b < BB; b++) g_cpart[(ks * BB + b) * DD + d] = acc[b];
    __threadfence();
    __shared__ unsigned done;
    if (threadIdx.x == 0) done = atomicAdd((unsigned*)&g_cnt[dt], 1u);
    __syncthreads();
    if (done == KS - 1) {
        #pragma unroll
        for (int b = 0; b < BB; b++) {
            float s = 0.f;
            #pragma unroll
            for (int k2 = 0; k2 < KS; k2++) s += g_cpart[(k2 * BB + b) * DD + d];
            Y[b * DD + d] = s;
        }
        __syncthreads();
        if (threadIdx.x == 0) g_cnt[dt] = 0;
    }
}

__global__ void __launch_bounds__(256) k_colmv(const float* __restrict__ M,
                                               const float* __restrict__ X,
                                               float* __restrict__ Y) {
    colmv_body(M, X, Y, blockIdx.x);
}

// ---------------- setup megakernel ----------------
// blocks [0,1024): Wgm = mean_g W_g ; [1024,1088): q0 = query @ W_h (colmv)
// blocks [1088,1096): b = mask? -1e18:0 ; c = softmax(b)
__global__ void __launch_bounds__(256) k_setup(const float* __restrict__ Wg,
                                               const float* __restrict__ Wh,
                                               const float* __restrict__ query,
                                               const unsigned* __restrict__ mask) {
    unsigned bid = blockIdx.x;
    if (bid < 1024) {
        int i = bid * 256 + threadIdx.x;
        const float4* W = (const float4*)Wg;
        float4 a = W[i], b = W[i + 262144], c = W[i + 524288], d = W[i + 786432];
        float4 r;
        r.x = 0.25f * (a.x + b.x + c.x + d.x);
        r.y = 0.25f * (a.y + b.y + c.y + d.y);
        r.z = 0.25f * (a.z + b.z + c.z + d.z);
        r.w = 0.25f * (a.w + b.w + c.w + d.w);
        ((float4*)g_Wgm)[i] = r;
    } else if (bid < 1024 + KS * DT) {
        colmv_body(Wh, query, g_q, (int)bid - 1024);
    } else {
        int b = (int)bid - (1024 + KS * DT);
        int t = threadIdx.x;
        float v[16];
        #pragma unroll
        for (int i = 0; i < 16; i++) {
            float bv = (mask[b * NN + i * 256 + t] != 0u) ? -1e18f : 0.0f;
            g_b[b * NN + i * 256 + t] = bv;
            v[i] = bv;
        }
        softmax_store(b, v);
    }
}

// ---------------- row-dot matvec: Y[b,r] = dot(M[r,:], X[b,:]) (+bias) ------
__global__ void __launch_bounds__(256) k_mv8(const float* __restrict__ M,
                                             const float* __restrict__ X,
                                             float* __restrict__ Y,
                                             const float* __restrict__ bias) {
    __shared__ float4 shX[BB * DD / 4];   // 32 KB
    const float4* Xv = (const float4*)X;
    #pragma unroll
    for (int i = threadIdx.x; i < BB * DD / 4; i += 256) shX[i] = Xv[i];
    __syncthreads();
    int warp = threadIdx.x >> 5, lane = threadIdx.x & 31;
    int r = blockIdx.x * 8 + warp;
    const float4* Mr = (const float4*)(M + (size_t)r * DD);
    float acc[BB];
    #pragma unroll
    for (int b = 0; b < BB; b++) acc[b] = 0.f;
    #pragma unroll
    for (int j = 0; j < 8; j++) {
        float4 m = Mr[j * 32 + lane];
        int base = j * 32 + lane;
        #pragma unroll
        for (int b = 0; b < BB; b++) {
            float4 xv = shX[b * (DD / 4) + base];
            acc[b] += m.x * xv.x + m.y * xv.y + m.z * xv.z + m.w * xv.w;
        }
    }
    #pragma unroll
    for (int b = 0; b < BB; b++) acc[b] = warpSum(acc[b]);
    if (lane == 0) {
        float bo = bias ? bias[r] : 0.f;
        #pragma unroll
        for (int b = 0; b < BB; b++) Y[b * DD + r] = acc[b] + bo;
    }
}

// ---------------- big streaming pass (double-buffered rows) ----------------
__global__ void __launch_bounds__(256) k_pass(const float* __restrict__ feat,
                                              int want_delta) {
    int b = blockIdx.y;
    int warp = threadIdx.x >> 5, lane = threadIdx.x & 31;
    __shared__ float4 sh_qt[DD / 4];
    __shared__ float sh_c[64];
    __shared__ float4 sh_s[DD / 4];
    const float4* qtv = (const float4*)(g_qt + b * DD);
    for (int i = threadIdx.x; i < DD / 4; i += 256) sh_qt[i] = qtv[i];
    if (threadIdx.x < 64) sh_c[threadIdx.x] = g_c[b * NN + blockIdx.x * 64 + threadIdx.x];
    __syncthreads();

    const float4* fb = (const float4*)feat + (size_t)b * NN * (DD / 4);
    int nbase = blockIdx.x * 64 + warp;      // rows: nbase + k*8, k=0..7

    float4 sacc[8];
    #pragma unroll
    for (int j = 0; j < 8; j++) sacc[j] = make_float4(0.f, 0.f, 0.f, 0.f);

    float4 cur[8];
    {
        const float4* rp = fb + (size_t)nbase * (DD / 4);
        #pragma unroll
        for (int j = 0; j < 8; j++) cur[j] = rp[j * 32 + lane];
    }
    #pragma unroll
    for (int k = 0; k < 8; k++) {
        float4 nxt[8];
        if (k < 7) {
            const float4* np = fb + (size_t)(nbase + (k + 1) * 8) * (DD / 4);
            #pragma unroll
            for (int j = 0; j < 8; j++) nxt[j] = np[j * 32 + lane];
        }
        float cw = sh_c[k * 8 + warp];
        float dp0 = 0.f, dp1 = 0.f;
        #pragma unroll
        for (int j = 0; j < 8; j++) {
            float4 qv = sh_qt[j * 32 + lane];
            dp0 += cur[j].x * qv.x + cur[j].y * qv.y;
            dp1 += cur[j].z * qv.z + cur[j].w * qv.w;
            sacc[j].x += cw * cur[j].x; sacc[j].y += cw * cur[j].y;
            sacc[j].z += cw * cur[j].z; sacc[j].w += cw * cur[j].w;
        }
        if (want_delta) {
            float dp = warpSum(dp0 + dp1);
            if (lane == 0) g_delta[b * NN + nbase + k * 8] = dp;
        }
        #pragma unroll
        for (int j = 0; j < 8; j++) cur[j] = nxt[j];
    }

    // deterministic staggered block-reduce of the 8 warps' s accumulators
    #pragma unroll
    for (int w = 0; w < 8; w++) {
        if (warp == w) {
            #pragma unroll
            for (int j = 0; j < 8; j++) {
                int idx = j * 32 + lane;
                if (w == 0) sh_s[idx] = sacc[j];
                else {
                    float4 t = sh_s[idx];
                    t.x += sacc[j].x; t.y += sacc[j].y;
                    t.z += sacc[j].z; t.w += sacc[j].w;
                    sh_s[idx] = t;
                }
            }
        }
        __syncthreads();
    }
    float4* pp = (float4*)(g_part + ((size_t)b * PASS_BLOCKS + blockIdx.x) * DD);
    for (int i = threadIdx.x; i < DD / 4; i += 256) pp[i] = sh_s[i];
}

// ---------------- fused: s-reduce (blocks 0..31) + b-update&softmax (32..39) -
__global__ void __launch_bounds__(256) k_sred_b(int want_b) {
    if (blockIdx.x < 32) {
        int i = blockIdx.x * 256 + threadIdx.x;   // < 8192
        int b = i >> 10, d = i & 1023;
        float acc = 0.f;
        #pragma unroll 8
        for (int k = 0; k < PASS_BLOCKS; k++)
            acc += g_part[((size_t)b * PASS_BLOCKS + k) * DD + d];
        g_sbuf[i] = acc;
    } else if (want_b) {
        int b = blockIdx.x - 32;
        int t = threadIdx.x;
        __shared__ float red2[16];
        float v[16];
        float s1 = 0.f, s2 = 0.f;
        #pragma unroll
        for (int i = 0; i < 16; i++) {
            v[i] = g_delta[b * NN + i * 256 + t];
            s1 += v[i]; s2 += v[i] * v[i];
        }
        s1 = warpSum(s1); s2 = warpSum(s2);
        if ((t & 31) == 0) { red2[t >> 5] = s1; red2[8 + (t >> 5)] = s2; }
        __syncthreads();
        s1 = 0.f; s2 = 0.f;
        #pragma unroll
        for (int w = 0; w < 8; w++) { s1 += red2[w]; s2 += red2[8 + w]; }
        float mean = s1 / (float)NN;
        float var = fmaxf((s2 - s1 * s1 / (float)NN) / (float)(NN - 1), 0.f);
        float inv = 1.0f / (sqrtf(var) + 1e-9f);
        #pragma unroll
        for (int i = 0; i < 16; i++) {
            float nb = g_b[b * NN + i * 256 + t] + (v[i] - mean) * inv;
            g_b[b * NN + i * 256 + t] = nb;
            v[i] = nb;
        }
        __syncthreads();
        softmax_store(b, v);
    }
}

// ---------------- q = LayerNorm(q + selu(outv*invn)) ----------------
__global__ void __launch_bounds__(256) k_qupd(const float* __restrict__ lnw,
                                              const float* __restrict__ lnb,
                                              float invn) {
    const float SELU_A = 1.6732632423543772f;
    const float SELU_S = 1.0507009873554805f;
    int b = blockIdx.x, t = threadIdx.x;
    __shared__ float red[16];
    float v[4];
    float s1 = 0.f, s2 = 0.f;
    #pragma unroll
    for (int i = 0; i < 4; i++) {
        int d = i * 256 + t;
        float x = g_outv[b * DD + d] * invn;
        float se = (x > 0.f) ? SELU_S * x : SELU_S * SELU_A * expm1f(x);
        v[i] = g_q[b * DD + d] + se;
        s1 += v[i]; s2 += v[i] * v[i];
    }
    s1 = warpSum(s1); s2 = warpSum(s2);
    if ((t & 31) == 0) { red[t >> 5] = s1; red[8 + (t >> 5)] = s2; }
    __syncthreads();
    s1 = 0.f; s2 = 0.f;
    #pragma unroll
    for (int w = 0; w < 8; w++) { s1 += red[w]; s2 += red[8 + w]; }
    float mu = s1 / (float)DD;
    float var = fmaxf(s2 / (float)DD - mu * mu, 0.f);
    float rstd = rsqrtf(var + 1e-5f);
    #pragma unroll
    for (int i = 0; i < 4; i++) {
        int d = i * 256 + t;
        g_q[b * DD + d] = (v[i] - mu) * rstd * lnw[d] + lnb[d];
    }
}

// ---------------- host orchestration ----------------
extern "C" void kernel_launch(void* const* d_in, const int* in_sizes, int n_in,
                              void* d_out, int out_size) {
    const float* query = (const float*)d_in[0];
    const float* feat  = (const float*)d_in[1];
    const float* W_h   = (const float*)d_in[2];
    const float* W_f   = (const float*)d_in[3];
    const float* W_g   = (const float*)d_in[4];
    const float* ln_w  = (const float*)d_in[5];
    const float* ln_b  = (const float*)d_in[6];
    const float* W_out = (const float*)d_in[7];
    const float* b_out = (const float*)d_in[8];
    const unsigned* mask = (const unsigned*)d_in[9];
    float* out = (float*)d_out;

    float *pWgm, *pQ, *pQt, *pTmp, *pTmp2, *pOutv, *pS;
    cudaGetSymbolAddress((void**)&pWgm,  g_Wgm);
    cudaGetSymbolAddress((void**)&pQ,    g_q);
    cudaGetSymbolAddress((void**)&pQt,   g_qt);
    cudaGetSymbolAddress((void**)&pTmp,  g_tmp);
    cudaGetSymbolAddress((void**)&pTmp2, g_tmp2);
    cudaGetSymbolAddress((void**)&pOutv, g_outv);
    cudaGetSymbolAddress((void**)&pS,    g_sbuf);

    // setup: Wgm mean | q0 colmv | mask->b->softmax, one launch
    k_setup<<<1024 + KS * DT + 8, 256>>>(W_g, W_h, query, mask);

    for (int it = 0; it < 3; it++) {
        bool last = (it == 2);
        if (!last) {
            k_colmv<<<KS * DT, 256>>>(pWgm, pQ, pTmp);        // tmp = Wgm^T q
            k_mv8<<<128, 256>>>(W_f, pTmp, pQt, nullptr);     // qt = W_f tmp
        }
        k_pass<<<dim3(PASS_BLOCKS, BB), 256>>>(feat, last ? 0 : 1);
        k_sred_b<<<last ? 32 : 40, 256>>>(last ? 0 : 1);      // s ; b+=norm(delta); c
        k_colmv<<<KS * DT, 256>>>(W_f, pS, pTmp2);            // tmp2 = W_f^T s
        k_mv8<<<128, 256>>>(pWgm, pTmp2, pOutv, nullptr);     // outv = Wgm tmp2
        k_qupd<<<8, 256>>>(ln_w, ln_b, last ? 1.0f : (1.0f / (float)NN));
    }
    k_mv8<<<128, 256>>>(W_out, pQ, out, b_out);               // out = q W_out^T + b_out
}

// round 3
// speedup vs baseline: 1.2533x; 1.2533x over previous
#include <cuda_runtime.h>

#define BB 8
#define NN 4096
#define DD 1024
#define NB 512          // total blocks; must be <= 4 * numSMs (148*4=592)
#define KS 16           // k-slices in column-GEMV
#define DT 4            // d-tiles in column-GEMV

// ---------------- device scratch (no allocations allowed) ----------------
__device__ __align__(16) float g_Wgm[DD * DD];
__device__ __align__(16) float g_b[BB * NN];
__device__ __align__(16) float g_c[BB * NN];
__device__ __align__(16) float g_delta[BB * NN];
__device__ __align__(16) float g_q[BB * DD];
__device__ __align__(16) float g_qt[BB * DD];
__device__ __align__(16) float g_tmp[BB * DD];
__device__ __align__(16) float g_tmp2[BB * DD];
__device__ __align__(16) float g_outv[BB * DD];
__device__ __align__(16) float g_sbuf[BB * DD];
__device__ __align__(16) float g_part[BB * 64 * DD];
__device__ __align__(16) float g_cpart[KS * BB * DD];
__device__ unsigned g_cnt[DT];        // zero-init, self-resetting
__device__ unsigned g_bar_count;      // zero-init, self-resetting
__device__ unsigned g_bar_sense;      // persists across runs; read at start

// ---------------- helpers ----------------
__device__ __forceinline__ float warpSum(float v) {
    #pragma unroll
    for (int o = 16; o; o >>= 1) v += __shfl_xor_sync(0xffffffffu, v, o);
    return v;
}
__device__ __forceinline__ float warpMax(float v) {
    #pragma unroll
    for (int o = 16; o; o >>= 1) v = fmaxf(v, __shfl_xor_sync(0xffffffffu, v, o));
    return v;
}

// grid-wide sense-reversing barrier. All NB blocks must call it the same
// number of times. __threadfence (gpu scope) flushes/invalidates L1D on
// sm_103a, giving cross-block visibility on both sides.
__device__ __forceinline__ void gbar(unsigned& sense) {
    __threadfence();
    __syncthreads();
    sense ^= 1u;
    if (threadIdx.x == 0) {
        unsigned a = atomicAdd(&g_bar_count, 1u);
        if (a == NB - 1) {
            g_bar_count = 0;
            __threadfence();
            atomicExch(&g_bar_sense, sense);
        } else {
            while (*(volatile unsigned*)&g_bar_sense != sense) __nanosleep(64);
        }
    }
    __syncthreads();
    __threadfence();
}

// softmax over 4096 values held 16/thread in v[]; writes g_c[b]. 256 threads.
__device__ void softmax_store(int b, float* v) {
    __shared__ float red[8];
    int t = threadIdx.x;
    float mx = -3.0e38f;
    #pragma unroll
    for (int i = 0; i < 16; i++) mx = fmaxf(mx, v[i]);
    mx = warpMax(mx);
    if ((t & 31) == 0) red[t >> 5] = mx;
    __syncthreads();
    mx = red[0];
    #pragma unroll
    for (int w = 1; w < 8; w++) mx = fmaxf(mx, red[w]);
    float sum = 0.f;
    #pragma unroll
    for (int i = 0; i < 16; i++) { v[i] = expf(v[i] - mx); sum += v[i]; }
    sum = warpSum(sum);
    __syncthreads();
    if ((t & 31) == 0) red[t >> 5] = sum;
    __syncthreads();
    sum = 0.f;
    #pragma unroll
    for (int w = 0; w < 8; w++) sum += red[w];
    float inv = 1.0f / sum;
    #pragma unroll
    for (int i = 0; i < 16; i++) g_c[b * NN + i * 256 + t] = v[i] * inv;
}

// column-GEMV: Y[b,d] = sum_k X[b,k] * M[k,d]. 64 blocks (cb in [0,64)).
// Last block per d-tile reduces KS slices in fixed order (deterministic).
__device__ void colmv(const float* __restrict__ M, const float* __restrict__ X,
                      float* __restrict__ Y, int cb) {
    __shared__ float sx[BB][64];
    __shared__ unsigned done;
    int dt = cb & (DT - 1);
    int ks = cb >> 2;
    int d = dt * 256 + threadIdx.x;
    for (int i = threadIdx.x; i < BB * 64; i += 256)
        sx[i >> 6][i & 63] = X[(i >> 6) * DD + ks * 64 + (i & 63)];
    __syncthreads();
    float acc[BB];
    #pragma unroll
    for (int b = 0; b < BB; b++) acc[b] = 0.f;
    const float* Mp = M + (size_t)(ks * 64) * DD + d;
    #pragma unroll 8
    for (int k = 0; k < 64; k++) {
        float m = Mp[(size_t)k * DD];
        #pragma unroll
        for (int b = 0; b < BB; b++) acc[b] += sx[b][k] * m;
    }
    #pragma unroll
    for (int b = 0; b < BB; b++) g_cpart[(ks * BB + b) * DD + d] = acc[b];
    __threadfence();
    __syncthreads();
    if (threadIdx.x == 0) done = atomicAdd(&g_cnt[dt], 1u);
    __syncthreads();
    if (done == KS - 1) {
        #pragma unroll
        for (int b = 0; b < BB; b++) {
            float s = 0.f;
            #pragma unroll
            for (int k2 = 0; k2 < KS; k2++)
                s += __ldcg(&g_cpart[(k2 * BB + b) * DD + d]);
            Y[b * DD + d] = s;
        }
        __syncthreads();
        if (threadIdx.x == 0) g_cnt[dt] = 0;
    }
}

// row-dot matvec over all NB blocks: Y[b,r] = dot(M[r,:], X[b,:]) (+bias).
// Block handles 2 rows; warp handles (row = 2*bid + (w&1), batches 2*(w>>1)+{0,1}).
__device__ void rowdot(const float* __restrict__ M, const float* __restrict__ X,
                       float* __restrict__ Y, const float* __restrict__ bias,
                       char* smraw) {
    float4* shX = (float4*)smraw;                  // 2048 float4 = 32 KB
    const float4* Xv = (const float4*)X;
    #pragma unroll
    for (int i = threadIdx.x; i < BB * DD / 4; i += 256) shX[i] = Xv[i];
    __syncthreads();
    int warp = threadIdx.x >> 5, lane = threadIdx.x & 31;
    int row = blockIdx.x * 2 + (warp & 1);
    int b0 = (warp >> 1) * 2;
    const float4* Mr = (const float4*)(M + (size_t)row * DD);
    float a0 = 0.f, a1 = 0.f;
    #pragma unroll
    for (int j = 0; j < 8; j++) {
        float4 m = Mr[j * 32 + lane];
        float4 x0 = shX[b0 * 256 + j * 32 + lane];
        float4 x1 = shX[(b0 + 1) * 256 + j * 32 + lane];
        a0 += m.x * x0.x + m.y * x0.y + m.z * x0.z + m.w * x0.w;
        a1 += m.x * x1.x + m.y * x1.y + m.z * x1.z + m.w * x1.w;
    }
    a0 = warpSum(a0); a1 = warpSum(a1);
    if (lane == 0) {
        float bo = bias ? bias[row] : 0.f;
        Y[(size_t)b0 * DD + row] = a0 + bo;
        Y[(size_t)(b0 + 1) * DD + row] = a1 + bo;
    }
    __syncthreads();
}

// big streaming pass: 512 blocks, block = (batch = bid>>6, chunk = bid&63).
// 8 warps = 4 teams x 2 half-rows. delta[b,n] = feat.qt, s-partials -> g_part.
__device__ void pass_phase(const float* __restrict__ feat, int want_delta,
                           char* smraw) {
    float4* sh_qt = (float4*)smraw;                 // 256 f4 (4 KB)
    float4* sh_s  = (float4*)(smraw + 4096);        // 256 f4 (4 KB)
    float*  sh_c  = (float*)(smraw + 8192);         // 64
    float*  sh_dp = (float*)(smraw + 8448);         // 128
    int b = blockIdx.x >> 6, chunk = blockIdx.x & 63;
    int warp = threadIdx.x >> 5, lane = threadIdx.x & 31;
    int team = warp >> 1, half = warp & 1;

    const float4* qtv = (const float4*)(g_qt + b * DD);
    for (int i = threadIdx.x; i < 256; i += 256) sh_qt[i] = qtv[i];
    if (threadIdx.x < 64) sh_c[threadIdx.x] = g_c[b * NN + chunk * 64 + threadIdx.x];
    __syncthreads();

    const float4* fb = (const float4*)feat + (size_t)b * NN * 256;
    float4 s0 = make_float4(0.f,0.f,0.f,0.f), s1 = s0, s2 = s0, s3 = s0;
    int base = half * 128 + lane;
    int nloc0 = team * 16;

    for (int k = 0; k < 16; k++) {
        int n = chunk * 64 + nloc0 + k;
        const float4* rp = fb + (size_t)n * 256 + base;
        float4 v0 = rp[0], v1 = rp[32], v2 = rp[64], v3 = rp[96];
        float4 q0 = sh_qt[base], q1 = sh_qt[base + 32],
               q2 = sh_qt[base + 64], q3 = sh_qt[base + 96];
        float cw = sh_c[nloc0 + k];
        float dp = v0.x*q0.x + v0.y*q0.y + v0.z*q0.z + v0.w*q0.w
                 + v1.x*q1.x + v1.y*q1.y + v1.z*q1.z + v1.w*q1.w
                 + v2.x*q2.x + v2.y*q2.y + v2.z*q2.z + v2.w*q2.w
                 + v3.x*q3.x + v3.y*q3.y + v3.z*q3.z + v3.w*q3.w;
        s0.x += cw*v0.x; s0.y += cw*v0.y; s0.z += cw*v0.z; s0.w += cw*v0.w;
        s1.x += cw*v1.x; s1.y += cw*v1.y; s1.z += cw*v1.z; s1.w += cw*v1.w;
        s2.x += cw*v2.x; s2.y += cw*v2.y; s2.z += cw*v2.z; s2.w += cw*v2.w;
        s3.x += cw*v3.x; s3.y += cw*v3.y; s3.z += cw*v3.z; s3.w += cw*v3.w;
        dp = warpSum(dp);
        if (lane == 0) sh_dp[warp * 16 + k] = dp;
    }
    __syncthreads();
    if (want_delta && threadIdx.x < 64) {
        int tm = threadIdx.x >> 4, k = threadIdx.x & 15;
        g_delta[b * NN + chunk * 64 + tm * 16 + k] =
            sh_dp[(2 * tm) * 16 + k] + sh_dp[(2 * tm + 1) * 16 + k];
    }
    // staggered deterministic s-reduce across the 4 teams (per half)
    #pragma unroll
    for (int w = 0; w < 4; w++) {
        if (team == w) {
            if (w == 0) {
                sh_s[base] = s0; sh_s[base + 32] = s1;
                sh_s[base + 64] = s2; sh_s[base + 96] = s3;
            } else {
                float4 t;
                t = sh_s[base];      t.x+=s0.x; t.y+=s0.y; t.z+=s0.z; t.w+=s0.w; sh_s[base]      = t;
                t = sh_s[base + 32]; t.x+=s1.x; t.y+=s1.y; t.z+=s1.z; t.w+=s1.w; sh_s[base + 32] = t;
                t = sh_s[base + 64]; t.x+=s2.x; t.y+=s2.y; t.z+=s2.z; t.w+=s2.w; sh_s[base + 64] = t;
                t = sh_s[base + 96]; t.x+=s3.x; t.y+=s3.y; t.z+=s3.z; t.w+=s3.w; sh_s[base + 96] = t;
            }
        }
        __syncthreads();
    }
    float4* pp = (float4*)(g_part + ((size_t)b * 64 + chunk) * DD);
    for (int i = threadIdx.x; i < 256; i += 256) pp[i] = sh_s[i];
    __syncthreads();
}

// s-partials reduce: blocks 0..31
__device__ void sred(int blk) {
    int i = blk * 256 + threadIdx.x;   // < 8192
    int b = i >> 10, d = i & 1023;
    float acc = 0.f;
    #pragma unroll 8
    for (int k = 0; k < 64; k++)
        acc += g_part[((size_t)b * 64 + k) * DD + d];
    g_sbuf[i] = acc;
}

// b += standardize(delta, ddof=1), then c = softmax(b). One block per batch.
__device__ void bupd(int b) {
    __shared__ float red2[16];
    int t = threadIdx.x;
    float v[16];
    float s1 = 0.f, s2 = 0.f;
    #pragma unroll
    for (int i = 0; i < 16; i++) {
        v[i] = g_delta[b * NN + i * 256 + t];
        s1 += v[i]; s2 += v[i] * v[i];
    }
    s1 = warpSum(s1); s2 = warpSum(s2);
    if ((t & 31) == 0) { red2[t >> 5] = s1; red2[8 + (t >> 5)] = s2; }
    __syncthreads();
    s1 = 0.f; s2 = 0.f;
    #pragma unroll
    for (int w = 0; w < 8; w++) { s1 += red2[w]; s2 += red2[8 + w]; }
    float mean = s1 / (float)NN;
    float var = fmaxf((s2 - s1 * s1 / (float)NN) / (float)(NN - 1), 0.f);
    float inv = 1.0f / (sqrtf(var) + 1e-9f);
    #pragma unroll
    for (int i = 0; i < 16; i++) {
        float nb = g_b[b * NN + i * 256 + t] + (v[i] - mean) * inv;
        g_b[b * NN + i * 256 + t] = nb;
        v[i] = nb;
    }
    __syncthreads();
    softmax_store(b, v);
}

// q = LayerNorm(q + selu(outv*invn)). One block per batch.
__device__ void qupd(int b, const float* __restrict__ lnw,
                     const float* __restrict__ lnb, float invn) {
    const float SELU_A = 1.6732632423543772f;
    const float SELU_S = 1.0507009873554805f;
    __shared__ float red[16];
    int t = threadIdx.x;
    float v[4];
    float s1 = 0.f, s2 = 0.f;
    #pragma unroll
    for (int i = 0; i < 4; i++) {
        int d = i * 256 + t;
        float x = g_outv[b * DD + d] * invn;
        float se = (x > 0.f) ? SELU_S * x : SELU_S * SELU_A * expm1f(x);
        v[i] = g_q[b * DD + d] + se;
        s1 += v[i]; s2 += v[i] * v[i];
    }
    s1 = warpSum(s1); s2 = warpSum(s2);
    if ((t & 31) == 0) { red[t >> 5] = s1; red[8 + (t >> 5)] = s2; }
    __syncthreads();
    s1 = 0.f; s2 = 0.f;
    #pragma unroll
    for (int w = 0; w < 8; w++) { s1 += red[w]; s2 += red[8 + w]; }
    float mu = s1 / (float)DD;
    float var = fmaxf(s2 / (float)DD - mu * mu, 0.f);
    float rstd = rsqrtf(var + 1e-5f);
    #pragma unroll
    for (int i = 0; i < 4; i++) {
        int d = i * 256 + t;
        g_q[b * DD + d] = (v[i] - mu) * rstd * lnw[d] + lnb[d];
    }
}

// ---------------- the one persistent megakernel ----------------
__global__ void __launch_bounds__(256, 4)
mega(const float* __restrict__ query, const float* __restrict__ feat,
     const float* __restrict__ Wh, const float* __restrict__ Wf,
     const float* __restrict__ Wg, const float* __restrict__ lnw,
     const float* __restrict__ lnb, const float* __restrict__ Wout,
     const float* __restrict__ bout, const unsigned* __restrict__ mask,
     float* __restrict__ out) {
    __shared__ __align__(16) char smraw[32768];
    unsigned sense = g_bar_sense;    // stable: no block can flip it before all read
    int bid = blockIdx.x;

    // ---- S1: Wgm = mean_g W_g  (all 512 blocks, 512 f4 each) ----
    {
        const float4* W = (const float4*)Wg;
        int i0 = bid * 512 + threadIdx.x;
        #pragma unroll
        for (int r = 0; r < 2; r++) {
            int i = i0 + r * 256;
            float4 a = W[i], b4 = W[i + 262144], c4 = W[i + 524288], d4 = W[i + 786432];
            float4 rr;
            rr.x = 0.25f * (a.x + b4.x + c4.x + d4.x);
            rr.y = 0.25f * (a.y + b4.y + c4.y + d4.y);
            rr.z = 0.25f * (a.z + b4.z + c4.z + d4.z);
            rr.w = 0.25f * (a.w + b4.w + c4.w + d4.w);
            ((float4*)g_Wgm)[i] = rr;
        }
    }
    gbar(sense);

    // ---- S2: q0 = query @ W_h (blocks 0..63)  |  b from mask + softmax (64..71) ----
    if (bid < 64) {
        colmv(Wh, query, g_q, bid);
    } else if (bid < 72) {
        int b = bid - 64, t = threadIdx.x;
        float v[16];
        #pragma unroll
        for (int i = 0; i < 16; i++) {
            float bv = (mask[b * NN + i * 256 + t] != 0u) ? -1e18f : 0.0f;
            g_b[b * NN + i * 256 + t] = bv;
            v[i] = bv;
        }
        softmax_store(b, v);
    }
    gbar(sense);

    for (int it = 0; it < 3; it++) {
        bool last = (it == 2);
        if (!last) {
            if (bid < 64) colmv(g_Wgm, g_q, g_tmp, bid);   // tmp = Wgm^T q
            gbar(sense);
            rowdot(Wf, g_tmp, g_qt, nullptr, smraw);       // qt = W_f tmp
            gbar(sense);
        }
        pass_phase(feat, last ? 0 : 1, smraw);             // delta, s-partials
        gbar(sense);
        if (bid < 32) sred(bid);                           // s
        else if (!last && bid < 40) bupd(bid - 32);        // b += norm(delta); c
        gbar(sense);
        if (bid < 64) colmv(Wf, g_sbuf, g_tmp2, bid);      // tmp2 = W_f^T s
        gbar(sense);
        rowdot(g_Wgm, g_tmp2, g_outv, nullptr, smraw);     // outv = Wgm tmp2
        gbar(sense);
        if (bid < 8) qupd(bid, lnw, lnb, last ? 1.0f : (1.0f / (float)NN));
        gbar(sense);
    }
    rowdot(Wout, g_q, out, bout, smraw);                   // out = q W_out^T + b_out
}

// ---------------- host orchestration: ONE launch ----------------
extern "C" void kernel_launch(void* const* d_in, const int* in_sizes, int n_in,
                              void* d_out, int out_size) {
    const float* query = (const float*)d_in[0];
    const float* feat  = (const float*)d_in[1];
    const float* W_h   = (const float*)d_in[2];
    const float* W_f   = (const float*)d_in[3];
    const float* W_g   = (const float*)d_in[4];
    const float* ln_w  = (const float*)d_in[5];
    const float* ln_b  = (const float*)d_in[6];
    const float* W_out = (const float*)d_in[7];
    const float* b_out = (const float*)d_in[8];
    const unsigned* mask = (const unsigned*)d_in[9];
    float* out = (float*)d_out;

    mega<<<NB, 256>>>(query, feat, W_h, W_f, W_g, ln_w, ln_b, W_out, b_out,
                      mask, out);
}

// round 4
// speedup vs baseline: 1.2557x; 1.0019x over previous
#include <cuda_runtime.h>

#define BB 8
#define NN 4096
#define DD 1024
#define NB 512          // total blocks; must be <= 4 * numSMs (148*4=592)
#define KS 16           // k-slices in column-GEMV
#define DT 4            // d-tiles in column-GEMV

// ---------------- device scratch (no allocations allowed) ----------------
__device__ __align__(16) float g_Wgm[DD * DD];
__device__ __align__(16) float g_b[BB * NN];
__device__ __align__(16) float g_c[BB * NN];
__device__ __align__(16) float g_delta[BB * NN];
__device__ __align__(16) float g_q[BB * DD];
__device__ __align__(16) float g_qt[BB * DD];
__device__ __align__(16) float g_tmp[BB * DD];
__device__ __align__(16) float g_tmp2[BB * DD];
__device__ __align__(16) float g_outv[BB * DD];
__device__ __align__(16) float g_sbuf[BB * DD];
__device__ __align__(16) float g_part[BB * 64 * DD];
__device__ __align__(16) float g_cpart[KS * BB * DD];
__device__ unsigned g_cnt[DT];        // zero-init, self-resetting
__device__ unsigned g_bar_count;      // zero-init, self-resetting
__device__ unsigned g_bar_sense;      // persists across runs; read at start

// ---------------- helpers ----------------
__device__ __forceinline__ float warpSum(float v) {
    #pragma unroll
    for (int o = 16; o; o >>= 1) v += __shfl_xor_sync(0xffffffffu, v, o);
    return v;
}
__device__ __forceinline__ float warpMax(float v) {
    #pragma unroll
    for (int o = 16; o; o >>= 1) v = fmaxf(v, __shfl_xor_sync(0xffffffffu, v, o));
    return v;
}

// grid-wide sense-reversing barrier. All NB blocks must call it the same
// number of times. __threadfence (gpu scope) flushes/invalidates L1D on
// sm_103a, giving cross-block visibility on both sides.
__device__ __forceinline__ void gbar(unsigned& sense) {
    __threadfence();
    __syncthreads();
    sense ^= 1u;
    if (threadIdx.x == 0) {
        unsigned a = atomicAdd(&g_bar_count, 1u);
        if (a == NB - 1) {
            g_bar_count = 0;
            __threadfence();
            atomicExch(&g_bar_sense, sense);
        } else {
            while (*(volatile unsigned*)&g_bar_sense != sense) __nanosleep(64);
        }
    }
    __syncthreads();
    __threadfence();
}

// softmax over 4096 values held 16/thread in v[]; writes g_c[b]. 256 threads.
__device__ void softmax_store(int b, float* v) {
    __shared__ float red[8];
    int t = threadIdx.x;
    float mx = -3.0e38f;
    #pragma unroll
    for (int i = 0; i < 16; i++) mx = fmaxf(mx, v[i]);
    mx = warpMax(mx);
    if ((t & 31) == 0) red[t >> 5] = mx;
    __syncthreads();
    mx = red[0];
    #pragma unroll
    for (int w = 1; w < 8; w++) mx = fmaxf(mx, red[w]);
    float sum = 0.f;
    #pragma unroll
    for (int i = 0; i < 16; i++) { v[i] = expf(v[i] - mx); sum += v[i]; }
    sum = warpSum(sum);
    __syncthreads();
    if ((t & 31) == 0) red[t >> 5] = sum;
    __syncthreads();
    sum = 0.f;
    #pragma unroll
    for (int w = 0; w < 8; w++) sum += red[w];
    float inv = 1.0f / sum;
    #pragma unroll
    for (int i = 0; i < 16; i++) g_c[b * NN + i * 256 + t] = v[i] * inv;
}

// column-GEMV: Y[b,d] = sum_k X[b,k] * M[k,d]. 64 blocks (cb in [0,64)).
// Last block per d-tile reduces KS slices in fixed order (deterministic).
__device__ void colmv(const float* __restrict__ M, const float* __restrict__ X,
                      float* __restrict__ Y, int cb) {
    __shared__ float sx[BB][64];
    __shared__ unsigned done;
    int dt = cb & (DT - 1);
    int ks = cb >> 2;
    int d = dt * 256 + threadIdx.x;
    for (int i = threadIdx.x; i < BB * 64; i += 256)
        sx[i >> 6][i & 63] = X[(i >> 6) * DD + ks * 64 + (i & 63)];
    __syncthreads();
    float acc[BB];
    #pragma unroll
    for (int b = 0; b < BB; b++) acc[b] = 0.f;
    const float* Mp = M + (size_t)(ks * 64) * DD + d;
    #pragma unroll 8
    for (int k = 0; k < 64; k++) {
        float m = Mp[(size_t)k * DD];
        #pragma unroll
        for (int b = 0; b < BB; b++) acc[b] += sx[b][k] * m;
    }
    #pragma unroll
    for (int b = 0; b < BB; b++) g_cpart[(ks * BB + b) * DD + d] = acc[b];
    __threadfence();
    __syncthreads();
    if (threadIdx.x == 0) done = atomicAdd(&g_cnt[dt], 1u);
    __syncthreads();
    if (done == KS - 1) {
        #pragma unroll
        for (int b = 0; b < BB; b++) {
            float s = 0.f;
            #pragma unroll
            for (int k2 = 0; k2 < KS; k2++)
                s += __ldcg(&g_cpart[(k2 * BB + b) * DD + d]);
            Y[b * DD + d] = s;
        }
        __syncthreads();
        if (threadIdx.x == 0) g_cnt[dt] = 0;
    }
}

// row-dot matvec over all NB blocks: Y[b,r] = dot(M[r,:], X[b,:]) (+bias).
// Block handles 2 rows; warp handles (row = 2*bid + (w&1), batches 2*(w>>1)+{0,1}).
__device__ void rowdot(const float* __restrict__ M, const float* __restrict__ X,
                       float* __restrict__ Y, const float* __restrict__ bias,
                       char* smraw) {
    float4* shX = (float4*)smraw;                  // 2048 float4 = 32 KB
    const float4* Xv = (const float4*)X;
    #pragma unroll
    for (int i = threadIdx.x; i < BB * DD / 4; i += 256) shX[i] = Xv[i];
    __syncthreads();
    int warp = threadIdx.x >> 5, lane = threadIdx.x & 31;
    int row = blockIdx.x * 2 + (warp & 1);
    int b0 = (warp >> 1) * 2;
    const float4* Mr = (const float4*)(M + (size_t)row * DD);
    float a0 = 0.f, a1 = 0.f;
    #pragma unroll
    for (int j = 0; j < 8; j++) {
        float4 m = Mr[j * 32 + lane];
        float4 x0 = shX[b0 * 256 + j * 32 + lane];
        float4 x1 = shX[(b0 + 1) * 256 + j * 32 + lane];
        a0 += m.x * x0.x + m.y * x0.y + m.z * x0.z + m.w * x0.w;
        a1 += m.x * x1.x + m.y * x1.y + m.z * x1.z + m.w * x1.w;
    }
    a0 = warpSum(a0); a1 = warpSum(a1);
    if (lane == 0) {
        float bo = bias ? bias[row] : 0.f;
        Y[(size_t)b0 * DD + row] = a0 + bo;
        Y[(size_t)(b0 + 1) * DD + row] = a1 + bo;
    }
    __syncthreads();
}

// big streaming pass: 512 blocks, block = (batch = bid>>6, chunk = bid&63).
// 8 warps = 4 teams x 2 half-rows. delta[b,n] = feat.qt, s-partials -> g_part.
__device__ void pass_phase(const float* __restrict__ feat, int want_delta,
                           char* smraw) {
    float4* sh_qt = (float4*)smraw;                 // 256 f4 (4 KB)
    float4* sh_s  = (float4*)(smraw + 4096);        // 256 f4 (4 KB)
    float*  sh_c  = (float*)(smraw + 8192);         // 64
    float*  sh_dp = (float*)(smraw + 8448);         // 128
    int b = blockIdx.x >> 6, chunk = blockIdx.x & 63;
    int warp = threadIdx.x >> 5, lane = threadIdx.x & 31;
    int team = warp >> 1, half = warp & 1;

    const float4* qtv = (const float4*)(g_qt + b * DD);
    for (int i = threadIdx.x; i < 256; i += 256) sh_qt[i] = qtv[i];
    if (threadIdx.x < 64) sh_c[threadIdx.x] = g_c[b * NN + chunk * 64 + threadIdx.x];
    __syncthreads();

    const float4* fb = (const float4*)feat + (size_t)b * NN * 256;
    float4 s0 = make_float4(0.f,0.f,0.f,0.f), s1 = s0, s2 = s0, s3 = s0;
    int base = half * 128 + lane;
    int nloc0 = team * 16;

    for (int k = 0; k < 16; k++) {
        int n = chunk * 64 + nloc0 + k;
        const float4* rp = fb + (size_t)n * 256 + base;
        float4 v0 = rp[0], v1 = rp[32], v2 = rp[64], v3 = rp[96];
        float4 q0 = sh_qt[base], q1 = sh_qt[base + 32],
               q2 = sh_qt[base + 64], q3 = sh_qt[base + 96];
        float cw = sh_c[nloc0 + k];
        float dp = v0.x*q0.x + v0.y*q0.y + v0.z*q0.z + v0.w*q0.w
                 + v1.x*q1.x + v1.y*q1.y + v1.z*q1.z + v1.w*q1.w
                 + v2.x*q2.x + v2.y*q2.y + v2.z*q2.z + v2.w*q2.w
                 + v3.x*q3.x + v3.y*q3.y + v3.z*q3.z + v3.w*q3.w;
        s0.x += cw*v0.x; s0.y += cw*v0.y; s0.z += cw*v0.z; s0.w += cw*v0.w;
        s1.x += cw*v1.x; s1.y += cw*v1.y; s1.z += cw*v1.z; s1.w += cw*v1.w;
        s2.x += cw*v2.x; s2.y += cw*v2.y; s2.z += cw*v2.z; s2.w += cw*v2.w;
        s3.x += cw*v3.x; s3.y += cw*v3.y; s3.z += cw*v3.z; s3.w += cw*v3.w;
        dp = warpSum(dp);
        if (lane == 0) sh_dp[warp * 16 + k] = dp;
    }
    __syncthreads();
    if (want_delta && threadIdx.x < 64) {
        int tm = threadIdx.x >> 4, k = threadIdx.x & 15;
        g_delta[b * NN + chunk * 64 + tm * 16 + k] =
            sh_dp[(2 * tm) * 16 + k] + sh_dp[(2 * tm + 1) * 16 + k];
    }
    // staggered deterministic s-reduce across the 4 teams (per half)
    #pragma unroll
    for (int w = 0; w < 4; w++) {
        if (team == w) {
            if (w == 0) {
                sh_s[base] = s0; sh_s[base + 32] = s1;
                sh_s[base + 64] = s2; sh_s[base + 96] = s3;
            } else {
                float4 t;
                t = sh_s[base];      t.x+=s0.x; t.y+=s0.y; t.z+=s0.z; t.w+=s0.w; sh_s[base]      = t;
                t = sh_s[base + 32]; t.x+=s1.x; t.y+=s1.y; t.z+=s1.z; t.w+=s1.w; sh_s[base + 32] = t;
                t = sh_s[base + 64]; t.x+=s2.x; t.y+=s2.y; t.z+=s2.z; t.w+=s2.w; sh_s[base + 64] = t;
                t = sh_s[base + 96]; t.x+=s3.x; t.y+=s3.y; t.z+=s3.z; t.w+=s3.w; sh_s[base + 96] = t;
            }
        }
        __syncthreads();
    }
    float4* pp = (float4*)(g_part + ((size_t)b * 64 + chunk) * DD);
    for (int i = threadIdx.x; i < 256; i += 256) pp[i] = sh_s[i];
    __syncthreads();
}

// s-partials reduce: blocks 0..31
__device__ void sred(int blk) {
    int i = blk * 256 + threadIdx.x;   // < 8192
    int b = i >> 10, d = i & 1023;
    float acc = 0.f;
    #pragma unroll 8
    for (int k = 0; k < 64; k++)
        acc += g_part[((size_t)b * 64 + k) * DD + d];
    g_sbuf[i] = acc;
}

// b += standardize(delta, ddof=1), then c = softmax(b). One block per batch.
__device__ void bupd(int b) {
    __shared__ float red2[16];
    int t = threadIdx.x;
    float v[16];
    float s1 = 0.f, s2 = 0.f;
    #pragma unroll
    for (int i = 0; i < 16; i++) {
        v[i] = g_delta[b * NN + i * 256 + t];
        s1 += v[i]; s2 += v[i] * v[i];
    }
    s1 = warpSum(s1); s2 = warpSum(s2);
    if ((t & 31) == 0) { red2[t >> 5] = s1; red2[8 + (t >> 5)] = s2; }
    __syncthreads();
    s1 = 0.f; s2 = 0.f;
    #pragma unroll
    for (int w = 0; w < 8; w++) { s1 += red2[w]; s2 += red2[8 + w]; }
    float mean = s1 / (float)NN;
    float var = fmaxf((s2 - s1 * s1 / (float)NN) / (float)(NN - 1), 0.f);
    float inv = 1.0f / (sqrtf(var) + 1e-9f);
    #pragma unroll
    for (int i = 0; i < 16; i++) {
        float nb = g_b[b * NN + i * 256 + t] + (v[i] - mean) * inv;
        g_b[b * NN + i * 256 + t] = nb;
        v[i] = nb;
    }
    __syncthreads();
    softmax_store(b, v);
}

// q = LayerNorm(q + selu(outv*invn)). One block per batch.
__device__ void qupd(int b, const float* __restrict__ lnw,
                     const float* __restrict__ lnb, float invn) {
    const float SELU_A = 1.6732632423543772f;
    const float SELU_S = 1.0507009873554805f;
    __shared__ float red[16];
    int t = threadIdx.x;
    float v[4];
    float s1 = 0.f, s2 = 0.f;
    #pragma unroll
    for (int i = 0; i < 4; i++) {
        int d = i * 256 + t;
        float x = g_outv[b * DD + d] * invn;
        float se = (x > 0.f) ? SELU_S * x : SELU_S * SELU_A * expm1f(x);
        v[i] = g_q[b * DD + d] + se;
        s1 += v[i]; s2 += v[i] * v[i];
    }
    s1 = warpSum(s1); s2 = warpSum(s2);
    if ((t & 31) == 0) { red[t >> 5] = s1; red[8 + (t >> 5)] = s2; }
    __syncthreads();
    s1 = 0.f; s2 = 0.f;
    #pragma unroll
    for (int w = 0; w < 8; w++) { s1 += red[w]; s2 += red[8 + w]; }
    float mu = s1 / (float)DD;
    float var = fmaxf(s2 / (float)DD - mu * mu, 0.f);
    float rstd = rsqrtf(var + 1e-5f);
    #pragma unroll
    for (int i = 0; i < 4; i++) {
        int d = i * 256 + t;
        g_q[b * DD + d] = (v[i] - mu) * rstd * lnw[d] + lnb[d];
    }
}

// ---------------- the one persistent megakernel ----------------
__global__ void __launch_bounds__(256, 4)
mega(const float* __restrict__ query, const float* __restrict__ feat,
     const float* __restrict__ Wh, const float* __restrict__ Wf,
     const float* __restrict__ Wg, const float* __restrict__ lnw,
     const float* __restrict__ lnb, const float* __restrict__ Wout,
     const float* __restrict__ bout, const unsigned* __restrict__ mask,
     float* __restrict__ out) {
    __shared__ __align__(16) char smraw[32768];
    unsigned sense = g_bar_sense;    // stable: no block can flip it before all read
    int bid = blockIdx.x;

    // ---- S1: Wgm = mean_g W_g  (all 512 blocks, 512 f4 each) ----
    {
        const float4* W = (const float4*)Wg;
        int i0 = bid * 512 + threadIdx.x;
        #pragma unroll
        for (int r = 0; r < 2; r++) {
            int i = i0 + r * 256;
            float4 a = W[i], b4 = W[i + 262144], c4 = W[i + 524288], d4 = W[i + 786432];
            float4 rr;
            rr.x = 0.25f * (a.x + b4.x + c4.x + d4.x);
            rr.y = 0.25f * (a.y + b4.y + c4.y + d4.y);
            rr.z = 0.25f * (a.z + b4.z + c4.z + d4.z);
            rr.w = 0.25f * (a.w + b4.w + c4.w + d4.w);
            ((float4*)g_Wgm)[i] = rr;
        }
    }
    gbar(sense);

    // ---- S2: q0 = query @ W_h (blocks 0..63)  |  b from mask + softmax (64..71) ----
    if (bid < 64) {
        colmv(Wh, query, g_q, bid);
    } else if (bid < 72) {
        int b = bid - 64, t = threadIdx.x;
        float v[16];
        #pragma unroll
        for (int i = 0; i < 16; i++) {
            float bv = (mask[b * NN + i * 256 + t] != 0u) ? -1e18f : 0.0f;
            g_b[b * NN + i * 256 + t] = bv;
            v[i] = bv;
        }
        softmax_store(b, v);
    }
    gbar(sense);

    for (int it = 0; it < 3; it++) {
        bool last = (it == 2);
        if (!last) {
            if (bid < 64) colmv(g_Wgm, g_q, g_tmp, bid);   // tmp = Wgm^T q
            gbar(sense);
            rowdot(Wf, g_tmp, g_qt, nullptr, smraw);       // qt = W_f tmp
            gbar(sense);
        }
        pass_phase(feat, last ? 0 : 1, smraw);             // delta, s-partials
        gbar(sense);
        if (bid < 32) sred(bid);                           // s
        else if (!last && bid < 40) bupd(bid - 32);        // b += norm(delta); c
        gbar(sense);
        if (bid < 64) colmv(Wf, g_sbuf, g_tmp2, bid);      // tmp2 = W_f^T s
        gbar(sense);
        rowdot(g_Wgm, g_tmp2, g_outv, nullptr, smraw);     // outv = Wgm tmp2
        gbar(sense);
        if (bid < 8) qupd(bid, lnw, lnb, last ? 1.0f : (1.0f / (float)NN));
        gbar(sense);
    }
    rowdot(Wout, g_q, out, bout, smraw);                   // out = q W_out^T + b_out
}

// ---------------- host orchestration: ONE launch ----------------
extern "C" void kernel_launch(void* const* d_in, const int* in_sizes, int n_in,
                              void* d_out, int out_size) {
    const float* query = (const float*)d_in[0];
    const float* feat  = (const float*)d_in[1];
    const float* W_h   = (const float*)d_in[2];
    const float* W_f   = (const float*)d_in[3];
    const float* W_g   = (const float*)d_in[4];
    const float* ln_w  = (const float*)d_in[5];
    const float* ln_b  = (const float*)d_in[6];
    const float* W_out = (const float*)d_in[7];
    const float* b_out = (const float*)d_in[8];
    const unsigned* mask = (const unsigned*)d_in[9];
    float* out = (float*)d_out;

    mega<<<NB, 256>>>(query, feat, W_h, W_f, W_g, ln_w, ln_b, W_out, b_out,
                      mask, out);
}

// round 5
// speedup vs baseline: 1.2858x; 1.0240x over previous
#include <cuda_runtime.h>

#define BB 8
#define NN 4096
#define DD 1024
#define NB 512          // all resident: 512 <= 4 * 148 SMs
#define KS 16           // k-slices in column-GEMV
#define DT 4            // d-tiles in column-GEMV

// ---------------- device scratch (no allocations allowed) ----------------
__device__ __align__(16) float g_Wgm[DD * DD];
__device__ __align__(16) float g_b[BB * NN];
__device__ __align__(16) float g_c[BB * NN];
__device__ __align__(16) float g_delta[BB * NN];
__device__ __align__(16) float g_qA[BB * DD];    // holds q0, later q2
__device__ __align__(16) float g_qB[BB * DD];    // holds q1
__device__ __align__(16) float g_tmp[BB * DD];
__device__ __align__(16) float g_tmp2[BB * DD];
__device__ __align__(16) float g_qt[BB * DD];
__device__ __align__(16) float g_outv[BB * DD];
__device__ __align__(16) float g_part[BB * 64 * DD];
__device__ __align__(16) float g_cpart[KS * BB * DD];
__device__ unsigned g_cnt[DT];        // zero-init, self-resetting
__device__ unsigned g_bar_count;      // zero-init, self-resetting
__device__ unsigned g_bar_sense;      // read at kernel start (any parity ok)

// ---------------- helpers ----------------
__device__ __forceinline__ float warpSum(float v) {
    #pragma unroll
    for (int o = 16; o; o >>= 1) v += __shfl_xor_sync(0xffffffffu, v, o);
    return v;
}
__device__ __forceinline__ float warpMax(float v) {
    #pragma unroll
    for (int o = 16; o; o >>= 1) v = fmaxf(v, __shfl_xor_sync(0xffffffffu, v, o));
    return v;
}
__device__ __forceinline__ float selu_f(float x) {
    const float A = 1.6732632423543772f, S = 1.0507009873554805f;
    return (x > 0.f) ? S * x : S * A * expm1f(x);
}

// grid-wide sense-reversing barrier; all NB blocks call it equally often.
__device__ __forceinline__ void gbar(unsigned& sense) {
    __threadfence();
    __syncthreads();
    sense ^= 1u;
    if (threadIdx.x == 0) {
        unsigned a = atomicAdd(&g_bar_count, 1u);
        if (a == NB - 1) {
            g_bar_count = 0;
            __threadfence();
            atomicExch(&g_bar_sense, sense);
        } else {
            while (*(volatile unsigned*)&g_bar_sense != sense) __nanosleep(32);
        }
    }
    __syncthreads();
    __threadfence();
}

// softmax over 4096 values held 16/thread in v[]; writes g_c[b]. 256 threads.
__device__ void softmax_store(int b, float* v) {
    __shared__ float red[8];
    int t = threadIdx.x;
    float mx = -3.0e38f;
    #pragma unroll
    for (int i = 0; i < 16; i++) mx = fmaxf(mx, v[i]);
    mx = warpMax(mx);
    if ((t & 31) == 0) red[t >> 5] = mx;
    __syncthreads();
    mx = red[0];
    #pragma unroll
    for (int w = 1; w < 8; w++) mx = fmaxf(mx, red[w]);
    float sum = 0.f;
    #pragma unroll
    for (int i = 0; i < 16; i++) { v[i] = expf(v[i] - mx); sum += v[i]; }
    sum = warpSum(sum);
    __syncthreads();
    if ((t & 31) == 0) red[t >> 5] = sum;
    __syncthreads();
    sum = 0.f;
    #pragma unroll
    for (int w = 0; w < 8; w++) sum += red[w];
    float inv = 1.0f / sum;
    #pragma unroll
    for (int i = 0; i < 16; i++) g_c[b * NN + i * 256 + t] = v[i] * inv;
}

// per-warp LN stats for batch b over v(d) = qold[d] + selu(outv[d]*invn)
__device__ __forceinline__ void q_stats(const float* __restrict__ qold,
                                        const float* __restrict__ outv,
                                        int b, float invn, int lane,
                                        float& mu, float& rstd) {
    float s1 = 0.f, s2 = 0.f;
    #pragma unroll 8
    for (int k = 0; k < 32; k++) {
        int d = k * 32 + lane;
        float v = qold[b * DD + d] + selu_f(outv[b * DD + d] * invn);
        s1 += v; s2 += v * v;
    }
    s1 = warpSum(s1); s2 = warpSum(s2);
    mu = s1 / (float)DD;
    float var = fmaxf(s2 / (float)DD - mu * mu, 0.f);
    rstd = rsqrtf(var + 1e-5f);
}

// shared compute tail of the split-K column-GEMV. sx[b][64] in smem.
// Y[b, dt*256+t] = sum over KS slices (cross-block, counter + fixed-order).
__device__ void colmv_compute(const float* __restrict__ M,
                              const float sx[BB][64], float* __restrict__ Y,
                              int dt, int ks) {
    __shared__ unsigned done;
    int d = dt * 256 + threadIdx.x;
    float acc[BB];
    #pragma unroll
    for (int b = 0; b < BB; b++) acc[b] = 0.f;
    const float* Mp = M + (size_t)(ks * 64) * DD + d;
    #pragma unroll 8
    for (int k = 0; k < 64; k++) {
        float m = Mp[(size_t)k * DD];
        #pragma unroll
        for (int b = 0; b < BB; b++) acc[b] += sx[b][k] * m;
    }
    #pragma unroll
    for (int b = 0; b < BB; b++) g_cpart[(ks * BB + b) * DD + d] = acc[b];
    __threadfence();
    __syncthreads();
    if (threadIdx.x == 0) done = atomicAdd(&g_cnt[dt], 1u);
    __syncthreads();
    if (done == KS - 1) {
        #pragma unroll
        for (int b = 0; b < BB; b++) {
            float s = 0.f;
            #pragma unroll
            for (int k2 = 0; k2 < KS; k2++)
                s += __ldcg(&g_cpart[(k2 * BB + b) * DD + d]);
            Y[b * DD + d] = s;
        }
        __syncthreads();
        if (threadIdx.x == 0) g_cnt[dt] = 0;
    }
}

// plain column-GEMV: X read from global
__device__ void colmv_plain(const float* __restrict__ M, const float* __restrict__ X,
                            float* __restrict__ Y, int cb) {
    __shared__ float sx[BB][64];
    int dt = cb & (DT - 1), ks = cb >> 2;
    for (int i = threadIdx.x; i < BB * 64; i += 256)
        sx[i >> 6][i & 63] = X[(i >> 6) * DD + ks * 64 + (i & 63)];
    __syncthreads();
    colmv_compute(M, sx, Y, dt, ks);
}

// column-GEMV with inline q-update: X = LN(qold + selu(outv*invn)).
// Warp w owns batch w. Block 0 persists full q to qdst.
__device__ void colmv_q(const float* __restrict__ M,
                        const float* __restrict__ qold,
                        const float* __restrict__ outv,
                        const float* __restrict__ lnw,
                        const float* __restrict__ lnb,
                        float invn, int write_q, float* __restrict__ qdst,
                        float* __restrict__ Y, int cb) {
    __shared__ float sx[BB][64];
    int warp = threadIdx.x >> 5, lane = threadIdx.x & 31;
    int dt = cb & (DT - 1), ks = cb >> 2;
    float mu, rstd;
    q_stats(qold, outv, warp, invn, lane, mu, rstd);
    #pragma unroll
    for (int j = 0; j < 2; j++) {
        int d = ks * 64 + j * 32 + lane;
        float v = qold[warp * DD + d] + selu_f(outv[warp * DD + d] * invn);
        sx[warp][j * 32 + lane] = (v - mu) * rstd * lnw[d] + lnb[d];
    }
    if (write_q) {
        #pragma unroll 4
        for (int k = 0; k < 32; k++) {
            int d = k * 32 + lane;
            float v = qold[warp * DD + d] + selu_f(outv[warp * DD + d] * invn);
            qdst[warp * DD + d] = (v - mu) * rstd * lnw[d] + lnb[d];
        }
    }
    __syncthreads();
    colmv_compute(M, sx, Y, dt, ks);
}

// column-GEMV fused with s-reduction: X[b,k] = sum over 64 chunks of g_part.
__device__ void colmv_s(const float* __restrict__ M, float* __restrict__ Y, int cb) {
    __shared__ float sx[BB][64];
    int dt = cb & (DT - 1), ks = cb >> 2;
    #pragma unroll
    for (int p = 0; p < 2; p++) {
        int idx = p * 256 + threadIdx.x;    // 512 (b,kk) pairs
        int b = idx >> 6, kk = idx & 63;
        const float* pp = g_part + (size_t)(b * 64) * DD + ks * 64 + kk;
        float a0 = 0.f, a1 = 0.f, a2 = 0.f, a3 = 0.f;
        #pragma unroll 4
        for (int c = 0; c < 64; c += 4) {
            a0 += pp[(size_t)c * DD];
            a1 += pp[(size_t)(c + 1) * DD];
            a2 += pp[(size_t)(c + 2) * DD];
            a3 += pp[(size_t)(c + 3) * DD];
        }
        sx[b][kk] = (a0 + a1) + (a2 + a3);
    }
    __syncthreads();
    colmv_compute(M, sx, Y, dt, ks);
}

// row-dot matvec over all NB blocks: Y[b,r] = dot(M[r,:], X[b,:]) (+bias).
__device__ void rowdot(const float* __restrict__ M, const float* __restrict__ X,
                       float* __restrict__ Y, const float* __restrict__ bias,
                       char* smraw) {
    float4* shX = (float4*)smraw;                  // 2048 f4 = 32 KB
    const float4* Xv = (const float4*)X;
    #pragma unroll
    for (int i = threadIdx.x; i < BB * DD / 4; i += 256) shX[i] = Xv[i];
    __syncthreads();
    int warp = threadIdx.x >> 5, lane = threadIdx.x & 31;
    int row = blockIdx.x * 2 + (warp & 1);
    int b0 = (warp >> 1) * 2;
    const float4* Mr = (const float4*)(M + (size_t)row * DD);
    float a0 = 0.f, a1 = 0.f;
    #pragma unroll
    for (int j = 0; j < 8; j++) {
        float4 m = Mr[j * 32 + lane];
        float4 x0 = shX[b0 * 256 + j * 32 + lane];
        float4 x1 = shX[(b0 + 1) * 256 + j * 32 + lane];
        a0 += m.x * x0.x + m.y * x0.y + m.z * x0.z + m.w * x0.w;
        a1 += m.x * x1.x + m.y * x1.y + m.z * x1.z + m.w * x1.w;
    }
    a0 = warpSum(a0); a1 = warpSum(a1);
    if (lane == 0) {
        float bo = bias ? bias[row] : 0.f;
        Y[(size_t)b0 * DD + row] = a0 + bo;
        Y[(size_t)(b0 + 1) * DD + row] = a1 + bo;
    }
    __syncthreads();
}

// final row-dot with inline q-update: X = LN(qold + selu(outv)).
__device__ void rowdot_q(const float* __restrict__ M,
                         const float* __restrict__ qold,
                         const float* __restrict__ outv,
                         const float* __restrict__ lnw,
                         const float* __restrict__ lnb,
                         float* __restrict__ Y, const float* __restrict__ bias,
                         char* smraw) {
    float* shX = (float*)smraw;                    // [8][1024] = 32 KB
    int warp = threadIdx.x >> 5, lane = threadIdx.x & 31;
    float mu, rstd;
    q_stats(qold, outv, warp, 1.0f, lane, mu, rstd);
    #pragma unroll 4
    for (int k = 0; k < 32; k++) {
        int d = k * 32 + lane;
        float v = qold[warp * DD + d] + selu_f(outv[warp * DD + d]);
        shX[warp * DD + d] = (v - mu) * rstd * lnw[d] + lnb[d];
    }
    __syncthreads();
    int row = blockIdx.x * 2 + (warp & 1);
    int b0 = (warp >> 1) * 2;
    const float4* Mr = (const float4*)(M + (size_t)row * DD);
    const float4* x0p = (const float4*)(shX + b0 * DD);
    const float4* x1p = (const float4*)(shX + (b0 + 1) * DD);
    float a0 = 0.f, a1 = 0.f;
    #pragma unroll
    for (int j = 0; j < 8; j++) {
        float4 m = Mr[j * 32 + lane];
        float4 x0 = x0p[j * 32 + lane];
        float4 x1 = x1p[j * 32 + lane];
        a0 += m.x * x0.x + m.y * x0.y + m.z * x0.z + m.w * x0.w;
        a1 += m.x * x1.x + m.y * x1.y + m.z * x1.z + m.w * x1.w;
    }
    a0 = warpSum(a0); a1 = warpSum(a1);
    if (lane == 0) {
        float bo = bias[row];
        Y[(size_t)b0 * DD + row] = a0 + bo;
        Y[(size_t)(b0 + 1) * DD + row] = a1 + bo;
    }
}

// big streaming pass: 512 blocks = (batch b = bid>>6, chunk = bid&63).
// Per-lane dp partials go to smem (no shfl in hot loop).
__device__ void pass_phase(const float* __restrict__ feat, int want_delta,
                           char* smraw) {
    float4* sh_qt = (float4*)smraw;                 // 4096 B
    float4* sh_s  = (float4*)(smraw + 4096);        // 4096 B
    float*  sh_c  = (float*)(smraw + 8192);         // 256 B
    float*  sh_dp = (float*)(smraw + 8448);         // 8*16*33*4 = 16896 B
    int b = blockIdx.x >> 6, chunk = blockIdx.x & 63;
    int warp = threadIdx.x >> 5, lane = threadIdx.x & 31;
    int team = warp >> 1, half = warp & 1;

    const float4* qtv = (const float4*)(g_qt + b * DD);
    sh_qt[threadIdx.x] = qtv[threadIdx.x];
    if (threadIdx.x < 64) sh_c[threadIdx.x] = g_c[b * NN + chunk * 64 + threadIdx.x];
    __syncthreads();

    int base = half * 128 + lane;
    float4 q0 = sh_qt[base], q1 = sh_qt[base + 32],
           q2 = sh_qt[base + 64], q3 = sh_qt[base + 96];
    float4 s0 = make_float4(0.f, 0.f, 0.f, 0.f), s1 = s0, s2 = s0, s3 = s0;
    const float4* fb = (const float4*)feat + (size_t)b * NN * 256;
    int n0 = chunk * 64 + team * 16;
    float* dpp = sh_dp + (size_t)(warp * 16) * 33 + lane;

    for (int k = 0; k < 16; k++) {
        const float4* rp = fb + (size_t)(n0 + k) * 256 + base;
        float4 v0 = __ldcs(rp), v1 = __ldcs(rp + 32),
               v2 = __ldcs(rp + 64), v3 = __ldcs(rp + 96);
        float cw = sh_c[team * 16 + k];
        float dp = v0.x*q0.x + v0.y*q0.y + v0.z*q0.z + v0.w*q0.w
                 + v1.x*q1.x + v1.y*q1.y + v1.z*q1.z + v1.w*q1.w
                 + v2.x*q2.x + v2.y*q2.y + v2.z*q2.z + v2.w*q2.w
                 + v3.x*q3.x + v3.y*q3.y + v3.z*q3.z + v3.w*q3.w;
        s0.x += cw*v0.x; s0.y += cw*v0.y; s0.z += cw*v0.z; s0.w += cw*v0.w;
        s1.x += cw*v1.x; s1.y += cw*v1.y; s1.z += cw*v1.z; s1.w += cw*v1.w;
        s2.x += cw*v2.x; s2.y += cw*v2.y; s2.z += cw*v2.z; s2.w += cw*v2.w;
        s3.x += cw*v3.x; s3.y += cw*v3.y; s3.z += cw*v3.z; s3.w += cw*v3.w;
        dpp[k * 33] = dp;
    }
    __syncthreads();
    if (want_delta && threadIdx.x < 64) {
        int tm = threadIdx.x >> 4, k = threadIdx.x & 15;
        const float* p0 = sh_dp + (size_t)((2 * tm) * 16 + k) * 33;
        const float* p1 = sh_dp + (size_t)((2 * tm + 1) * 16 + k) * 33;
        float acc = 0.f;
        #pragma unroll
        for (int l = 0; l < 32; l++) acc += p0[l] + p1[l];
        g_delta[b * NN + chunk * 64 + threadIdx.x] = acc;
    }
    // staggered deterministic s-reduce across the 4 teams (per half)
    #pragma unroll
    for (int w = 0; w < 4; w++) {
        if (team == w) {
            if (w == 0) {
                sh_s[base] = s0; sh_s[base + 32] = s1;
                sh_s[base + 64] = s2; sh_s[base + 96] = s3;
            } else {
                float4 t;
                t = sh_s[base];      t.x+=s0.x; t.y+=s0.y; t.z+=s0.z; t.w+=s0.w; sh_s[base]      = t;
                t = sh_s[base + 32]; t.x+=s1.x; t.y+=s1.y; t.z+=s1.z; t.w+=s1.w; sh_s[base + 32] = t;
                t = sh_s[base + 64]; t.x+=s2.x; t.y+=s2.y; t.z+=s2.z; t.w+=s2.w; sh_s[base + 64] = t;
                t = sh_s[base + 96]; t.x+=s3.x; t.y+=s3.y; t.z+=s3.z; t.w+=s3.w; sh_s[base + 96] = t;
            }
        }
        __syncthreads();
    }
    float4* pp = (float4*)(g_part + ((size_t)b * 64 + chunk) * DD);
    pp[threadIdx.x] = sh_s[threadIdx.x];
    __syncthreads();
}

// b += standardize(delta, ddof=1), then c = softmax(b). One block per batch.
__device__ void bupd(int b) {
    __shared__ float red2[16];
    int t = threadIdx.x;
    float v[16];
    float s1 = 0.f, s2 = 0.f;
    #pragma unroll
    for (int i = 0; i < 16; i++) {
        v[i] = g_delta[b * NN + i * 256 + t];
        s1 += v[i]; s2 += v[i] * v[i];
    }
    s1 = warpSum(s1); s2 = warpSum(s2);
    if ((t & 31) == 0) { red2[t >> 5] = s1; red2[8 + (t >> 5)] = s2; }
    __syncthreads();
    s1 = 0.f; s2 = 0.f;
    #pragma unroll
    for (int w = 0; w < 8; w++) { s1 += red2[w]; s2 += red2[8 + w]; }
    float mean = s1 / (float)NN;
    float var = fmaxf((s2 - s1 * s1 / (float)NN) / (float)(NN - 1), 0.f);
    float inv = 1.0f / (sqrtf(var) + 1e-9f);
    #pragma unroll
    for (int i = 0; i < 16; i++) {
        float nb = g_b[b * NN + i * 256 + t] + (v[i] - mean) * inv;
        g_b[b * NN + i * 256 + t] = nb;
        v[i] = nb;
    }
    __syncthreads();
    softmax_store(b, v);
}

// standalone q-update for one batch (256 threads): qdst = LN(qold+selu(outv*invn))
__device__ void qupd_block(int b, const float* __restrict__ qold,
                           const float* __restrict__ outv,
                           const float* __restrict__ lnw,
                           const float* __restrict__ lnb,
                           float invn, float* __restrict__ qdst) {
    __shared__ float red[16];
    int t = threadIdx.x;
    float v[4];
    float s1 = 0.f, s2 = 0.f;
    #pragma unroll
    for (int i = 0; i < 4; i++) {
        int d = i * 256 + t;
        v[i] = qold[b * DD + d] + selu_f(outv[b * DD + d] * invn);
        s1 += v[i]; s2 += v[i] * v[i];
    }
    s1 = warpSum(s1); s2 = warpSum(s2);
    if ((t & 31) == 0) { red[t >> 5] = s1; red[8 + (t >> 5)] = s2; }
    __syncthreads();
    s1 = 0.f; s2 = 0.f;
    #pragma unroll
    for (int w = 0; w < 8; w++) { s1 += red[w]; s2 += red[8 + w]; }
    float mu = s1 / (float)DD;
    float var = fmaxf(s2 / (float)DD - mu * mu, 0.f);
    float rstd = rsqrtf(var + 1e-5f);
    #pragma unroll
    for (int i = 0; i < 4; i++) {
        int d = i * 256 + t;
        qdst[b * DD + d] = (v[i] - mu) * rstd * lnw[d] + lnb[d];
    }
}

// NOTE: for per-warp q_stats, variance uses E[v^2]-mu^2 (biased), matching jnp.var.

// ---------------- the one persistent megakernel ----------------
__global__ void __launch_bounds__(256, 4)
mega(const float* __restrict__ query, const float* __restrict__ feat,
     const float* __restrict__ Wh, const float* __restrict__ Wf,
     const float* __restrict__ Wg, const float* __restrict__ lnw,
     const float* __restrict__ lnb, const float* __restrict__ Wout,
     const float* __restrict__ bout, const unsigned* __restrict__ mask,
     float* __restrict__ out) {
    __shared__ __align__(16) char smraw[32768];
    unsigned sense = g_bar_sense;   // read before any block can flip it
    int bid = blockIdx.x;
    const float INVN = 1.0f / (float)NN;

    // ---- S1: Wgm = mean_g W_g ----
    {
        const float4* W = (const float4*)Wg;
        int i0 = bid * 512 + threadIdx.x;
        #pragma unroll
        for (int r = 0; r < 2; r++) {
            int i = i0 + r * 256;
            float4 a = __ldcs(W + i), b4 = __ldcs(W + i + 262144),
                   c4 = __ldcs(W + i + 524288), d4 = __ldcs(W + i + 786432);
            float4 rr;
            rr.x = 0.25f * (a.x + b4.x + c4.x + d4.x);
            rr.y = 0.25f * (a.y + b4.y + c4.y + d4.y);
            rr.z = 0.25f * (a.z + b4.z + c4.z + d4.z);
            rr.w = 0.25f * (a.w + b4.w + c4.w + d4.w);
            ((float4*)g_Wgm)[i] = rr;
        }
    }
    gbar(sense);

    // ---- S2: q0 = query @ W_h (0..63) | b from mask + softmax (64..71) ----
    if (bid < 64) {
        colmv_plain(Wh, query, g_qA, bid);
    } else if (bid < 72) {
        int b = bid - 64, t = threadIdx.x;
        float v[16];
        #pragma unroll
        for (int i = 0; i < 16; i++) {
            float bv = (mask[b * NN + i * 256 + t] != 0u) ? -1e18f : 0.0f;
            g_b[b * NN + i * 256 + t] = bv;
            v[i] = bv;
        }
        softmax_store(b, v);
    }
    gbar(sense);

    // ======== iteration 0 (q = q0 in g_qA) ========
    if (bid < 64) colmv_plain(g_Wgm, g_qA, g_tmp, bid);      // tmp = Wgm^T q0
    gbar(sense);
    rowdot(Wf, g_tmp, g_qt, nullptr, smraw);                 // qt = W_f tmp
    gbar(sense);
    pass_phase(feat, 1, smraw);                              // delta, s-partials
    gbar(sense);
    if (bid < 64) colmv_s(Wf, g_tmp2, bid);                  // tmp2 = W_f^T s
    else if (bid < 72) bupd(bid - 64);                       // b+=norm(delta); c
    gbar(sense);
    rowdot(g_Wgm, g_tmp2, g_outv, nullptr, smraw);           // outv0 = Wgm tmp2
    gbar(sense);

    // ======== iteration 1 (q1 = LN(q0+selu(outv0/n)) inline) ========
    if (bid < 64) colmv_q(g_Wgm, g_qA, g_outv, lnw, lnb, INVN,
                          (bid == 0), g_qB, g_tmp, bid);     // tmp = Wgm^T q1
    gbar(sense);
    rowdot(Wf, g_tmp, g_qt, nullptr, smraw);                 // qt = W_f tmp
    gbar(sense);
    pass_phase(feat, 1, smraw);
    gbar(sense);
    if (bid < 64) colmv_s(Wf, g_tmp2, bid);
    else if (bid < 72) bupd(bid - 64);
    gbar(sense);
    rowdot(g_Wgm, g_tmp2, g_outv, nullptr, smraw);           // outv1
    gbar(sense);

    // ======== iteration 2 (last; uses c2 from it1's bupd, no qt/delta) ========
    pass_phase(feat, 0, smraw);                              // s-partials only
    gbar(sense);
    if (bid < 64) colmv_s(Wf, g_tmp2, bid);                  // tmp2 = W_f^T s
    else if (bid < 72) qupd_block(bid - 64, g_qB, g_outv,
                                  lnw, lnb, INVN, g_qA);     // q2 -> g_qA
    gbar(sense);
    rowdot(g_Wgm, g_tmp2, g_outv, nullptr, smraw);           // outv2
    gbar(sense);
    // out = LN(q2 + selu(outv2)) @ W_out^T + b_out   (q3 inline)
    rowdot_q(Wout, g_qA, g_outv, lnw, lnb, out, bout, smraw);
}

// ---------------- host orchestration: ONE launch ----------------
extern "C" void kernel_launch(void* const* d_in, const int* in_sizes, int n_in,
                              void* d_out, int out_size) {
    const float* query = (const float*)d_in[0];
    const float* feat  = (const float*)d_in[1];
    const float* W_h   = (const float*)d_in[2];
    const float* W_f   = (const float*)d_in[3];
    const float* W_g   = (const float*)d_in[4];
    const float* ln_w  = (const float*)d_in[5];
    const float* ln_b  = (const float*)d_in[6];
    const float* W_out = (const float*)d_in[7];
    const float* b_out = (const float*)d_in[8];
    const unsigned* mask = (const unsigned*)d_in[9];
    float* out = (float*)d_out;

    mega<<<NB, 256>>>(query, feat, W_h, W_f, W_g, ln_w, ln_b, W_out, b_out,
                      mask, out);
}